// round 17
// baseline (speedup 1.0000x reference)
#include <cuda_runtime.h>
#include <cuda_bf16.h>

// Problem: B=64, L=1024, D=1280
//   pool_len = lengths + 2
//   emb[b,d]  = mean over l < pool_len of prev[b,l,d]
//   x         = relu(emb @ dense_w + dense_b)        [64,1280]
//   out       = x @ cls_w + cls_b                    [64,1]
//
// TWO launches:
//  1) pool_kernel : 592 blocks x 320 thr (proven best, 37us). Exact task list
//     over valid 64-row segments; last block per b reduces partials, writes
//     embT[k][b]. Also prefetches dense_w into L2 (evict_last) and block 0
//     initializes out[b] = cls_b.
//  2) fused_kernel: grid(40 j-tiles, 2 b-halves) x 256 thr. Each block owns
//     x[32b x 32j] with the FULL k=1280 (no k-split, no xpart round-trip),
//     applies bias+relu, dots with cls_w, warp-reduces over j, atomicAdds
//     per-b partials into out. One kernel replaces gemm+final.

#define Bq     64
#define Lq     1024
#define Dq     1280
#define D4     320           // float4 per row
#define SEGR   64            // rows per pool segment
#define MAXSEG 16
#define GPOOL  592           // pool blocks

#define NJ2    40            // j tiles of 32
#define JT2    32
#define KC2    80            // k per smem stage (16 stages)

#define WLINES ((Dq * Dq * 4) / 128)             // 51200 128B lines of W
#define LPB    ((WLINES + GPOOL - 1) / GPOOL)    // 87 lines per pool block

typedef unsigned long long u64;

// scratch (allocation-free: __device__ globals)
__device__ float    g_part[Bq * MAXSEG * Dq];   // pool partials (5.24 MB)
__device__ float    g_embT[Dq * Bq];            // emb transposed [k][b]
__device__ unsigned g_cnt [Bq];                 // pool arrival counters

// packed f32x2 FMA (SASS FFMA2)
__device__ __forceinline__ u64 ffma2(u64 a, u64 b, u64 c) {
    u64 d;
    asm("fma.rn.f32x2 %0, %1, %2, %3;" : "=l"(d) : "l"(a), "l"(b), "l"(c));
    return d;
}
__device__ __forceinline__ u64 pack2(float lo, float hi) {
    u64 d;
    asm("mov.b64 %0, {%1, %2};" : "=l"(d) : "f"(lo), "f"(hi));
    return d;
}
__device__ __forceinline__ void unpack2(u64 v, float& lo, float& hi) {
    asm("mov.b64 {%0, %1}, %2;" : "=f"(lo), "=f"(hi) : "l"(v));
}

// ---------------------------------------------------------------------------
// Kernel 1: balanced ragged pool + fused per-b reduction + W prefetch + init.
// ---------------------------------------------------------------------------
__global__ void __launch_bounds__(D4) pool_kernel(
    const float* __restrict__ prev, const int* __restrict__ lengths,
    const float* __restrict__ W, const float* __restrict__ cls_b,
    float* __restrict__ out)
{
    __shared__ int s_pre[Bq + 1];
    __shared__ int s_last;

    const int tid = threadIdx.x;
    const int bid = blockIdx.x;

    if (bid == 0 && tid < Bq)                     // init out for fused atomics
        out[tid] = cls_b[0];

    if (tid == 0) {
        int acc = 0;
        s_pre[0] = 0;
        for (int b = 0; b < Bq; ++b) {
            int pl = lengths[b] + 2;
            acc += (pl + SEGR - 1) >> 6;          // ceil(pl/64)
            s_pre[b + 1] = acc;
        }
    }
    __syncthreads();
    const int S = s_pre[Bq];                      // total valid segments

    for (int t = bid; t < S; t += GPOOL) {
        // binary search: b with s_pre[b] <= t < s_pre[b+1]
        int lo = 0, hi = Bq;
        while (hi - lo > 1) {
            int m = (lo + hi) >> 1;
            if (s_pre[m] <= t) lo = m; else hi = m;
        }
        const int b    = lo;
        const int seg  = t - s_pre[b];
        const int pl   = lengths[b] + 2;
        const int l0   = seg * SEGR;
        const int n    = min(SEGR, pl - l0);      // >= 1 by construction
        const int nseg = s_pre[b + 1] - s_pre[b];

        float4 a0 = make_float4(0.f, 0.f, 0.f, 0.f);
        float4 a1 = a0, a2 = a0, a3 = a0;

        const float4* __restrict__ p =
            reinterpret_cast<const float4*>(prev) + ((size_t)b * Lq + l0) * D4 + tid;
        int l = 0;
        for (; l + 8 <= n; l += 8) {
            float4 v0 = p[(size_t)(l + 0) * D4];
            float4 v1 = p[(size_t)(l + 1) * D4];
            float4 v2 = p[(size_t)(l + 2) * D4];
            float4 v3 = p[(size_t)(l + 3) * D4];
            float4 v4 = p[(size_t)(l + 4) * D4];
            float4 v5 = p[(size_t)(l + 5) * D4];
            float4 v6 = p[(size_t)(l + 6) * D4];
            float4 v7 = p[(size_t)(l + 7) * D4];
            a0.x += v0.x; a0.y += v0.y; a0.z += v0.z; a0.w += v0.w;
            a1.x += v1.x; a1.y += v1.y; a1.z += v1.z; a1.w += v1.w;
            a2.x += v2.x; a2.y += v2.y; a2.z += v2.z; a2.w += v2.w;
            a3.x += v3.x; a3.y += v3.y; a3.z += v3.z; a3.w += v3.w;
            a0.x += v4.x; a0.y += v4.y; a0.z += v4.z; a0.w += v4.w;
            a1.x += v5.x; a1.y += v5.y; a1.z += v5.z; a1.w += v5.w;
            a2.x += v6.x; a2.y += v6.y; a2.z += v6.z; a2.w += v6.w;
            a3.x += v7.x; a3.y += v7.y; a3.z += v7.z; a3.w += v7.w;
        }
        for (; l < n; ++l) {
            float4 v = p[(size_t)l * D4];
            a0.x += v.x; a0.y += v.y; a0.z += v.z; a0.w += v.w;
        }
        float4 s;
        s.x = (a0.x + a1.x) + (a2.x + a3.x);
        s.y = (a0.y + a1.y) + (a2.y + a3.y);
        s.z = (a0.z + a1.z) + (a2.z + a3.z);
        s.w = (a0.w + a1.w) + (a2.w + a3.w);
        reinterpret_cast<float4*>(g_part)[((size_t)b * MAXSEG + seg) * D4 + tid] = s;

        // publish partial, count arrival; last arrival reduces this b
        __threadfence();
        __syncthreads();
        if (tid == 0) {
            unsigned old = atomicAdd(&g_cnt[b], 1u);
            s_last = (((old + 1u) % (unsigned)nseg) == 0u) ? 1 : 0;
        }
        __syncthreads();
        if (s_last) {
            __threadfence();   // acquire other blocks' partials
            const float4* gp = reinterpret_cast<const float4*>(g_part)
                               + (size_t)b * MAXSEG * D4 + tid;
            float4 r = make_float4(0.f, 0.f, 0.f, 0.f);
            for (int sg = 0; sg < nseg; ++sg) {
                float4 v = gp[(size_t)sg * D4];
                r.x += v.x; r.y += v.y; r.z += v.z; r.w += v.w;
            }
            const float inv = 1.0f / (float)pl;
            r.x *= inv; r.y *= inv; r.z *= inv; r.w *= inv;
            g_embT[(size_t)(4 * tid + 0) * Bq + b] = r.x;
            g_embT[(size_t)(4 * tid + 1) * Bq + b] = r.y;
            g_embT[(size_t)(4 * tid + 2) * Bq + b] = r.z;
            g_embT[(size_t)(4 * tid + 3) * Bq + b] = r.w;
        }
        __syncthreads();       // protect s_last across task iterations
    }

    // ---- prefetch this block's slice of dense_w into L2 (evict_last) ----
    {
        const char* wb = reinterpret_cast<const char*>(W);
        int line = bid * LPB + tid;
        if (tid < LPB && line < WLINES) {
            asm volatile("prefetch.global.L2::evict_last [%0];"
                         :: "l"(wb + (size_t)line * 128));
        }
    }
}

// ---------------------------------------------------------------------------
// Kernel 2: fused GEMM + bias + relu + cls dot + atomic out.
// grid(NJ2=40, 2), 256 threads. Block tile: 32b x 32j, full k=1280.
// Thread tile 2b x 2j; FFMA2 inner (2 LDS / 2 FFMA2 per kk, broadcast-heavy).
// ---------------------------------------------------------------------------
__global__ void __launch_bounds__(256) fused_kernel(
    const float* __restrict__ W,
    const float* __restrict__ dense_b,
    const float* __restrict__ cls_w,
    float* __restrict__ out)
{
    __shared__ __align__(16) float sE[KC2][JT2];   // embT chunk (b-half) 10 KB
    __shared__ __align__(16) float sW[KC2][JT2];   // W chunk            10 KB

    const int tid = threadIdx.x;
    const int jx  = blockIdx.x;                    // 0..39
    const int bh  = blockIdx.y;                    // 0..1
    const int j0  = jx * JT2;
    const int b0  = bh * 32;
    const int bg  = tid >> 4;                      // 0..15 -> b = b0+2bg, +1
    const int jg  = tid & 15;                      // 0..15 -> j = j0+2jg, +1

    u64 acc0 = 0ull, acc1 = 0ull;   // lanes: (b_lo, b_hi) for j 2jg / 2jg+1

    for (int c = 0; c < Dq; c += KC2) {
        __syncthreads();
        // stage embT chunk (b-half): rows of 32 consecutive b -> coalesced
        for (int i = tid; i < KC2 * JT2; i += 256) {
            int kk = i >> 5;
            int bb = i & 31;
            sE[kk][bb] = g_embT[(size_t)(c + kk) * Bq + b0 + bb];
        }
        // stage W chunk: rows of 32 consecutive j -> coalesced
        for (int i = tid; i < KC2 * JT2; i += 256) {
            int kk = i >> 5;
            int jj = i & 31;
            sW[kk][jj] = W[(size_t)(c + kk) * Dq + j0 + jj];
        }
        __syncthreads();

#pragma unroll 16
        for (int kk = 0; kk < KC2; ++kk) {
            float2 e = *reinterpret_cast<const float2*>(&sE[kk][2 * bg]);
            float2 w = *reinterpret_cast<const float2*>(&sW[kk][2 * jg]);
            u64 e01 = pack2(e.x, e.y);
            u64 wx  = pack2(w.x, w.x);
            u64 wy  = pack2(w.y, w.y);
            acc0 = ffma2(e01, wx, acc0);
            acc1 = ffma2(e01, wy, acc1);
        }
    }

    // epilogue: bias + relu + cls weight, per-thread partial per b
    float x00, x10, x01, x11;      // x[b0+2bg][j], x[b0+2bg+1][j]
    unpack2(acc0, x00, x10);       // j = j0 + 2jg
    unpack2(acc1, x01, x11);       // j = j0 + 2jg + 1

    const int ja = j0 + 2 * jg;
    const float bja = dense_b[ja], bjb = dense_b[ja + 1];
    const float cja = cls_w[ja],   cjb = cls_w[ja + 1];

    float p0 = fmaxf(x00 + bja, 0.f) * cja + fmaxf(x01 + bjb, 0.f) * cjb;
    float p1 = fmaxf(x10 + bja, 0.f) * cja + fmaxf(x11 + bjb, 0.f) * cjb;

    // reduce over jg (low 4 lane bits); lane>>4 selects bg parity, untouched
#pragma unroll
    for (int o = 8; o > 0; o >>= 1) {
        p0 += __shfl_xor_sync(0xffffffffu, p0, o);
        p1 += __shfl_xor_sync(0xffffffffu, p1, o);
    }
    if ((tid & 15) == 0) {
        const int b = b0 + 2 * bg;
        atomicAdd(&out[b],     p0);   // 40 partials per output value
        atomicAdd(&out[b + 1], p1);
    }
}

// ---------------------------------------------------------------------------
extern "C" void kernel_launch(void* const* d_in, const int* in_sizes, int n_in,
                              void* d_out, int out_size)
{
    const float* prev    = (const float*)d_in[0];
    const int*   lengths = (const int*)  d_in[1];
    const float* dense_w = (const float*)d_in[2];
    const float* dense_b = (const float*)d_in[3];
    const float* cls_w   = (const float*)d_in[4];
    const float* cls_b   = (const float*)d_in[5];
    float*       out     = (float*)d_out;

    pool_kernel <<<GPOOL, D4>>>(prev, lengths, dense_w, cls_b, out);
    fused_kernel<<<dim3(NJ2, 2), 256>>>(dense_w, dense_b, cls_w, out);
}